// round 16
// baseline (speedup 1.0000x reference)
#include <cuda_runtime.h>
#include <cuda_fp16.h>
#include <math.h>
#include <stdint.h>

// Problem constants
#define BB 2
#define SS 2048
#define DD 1024
#define HH 16
#define HD 64
#define FFN 4096
#define MM (BB*SS)          // 4096 rows
#define EPS_RMS 1.1920929e-07f

// ---------------- scratch (device globals; allocation-free) ----------------
static __device__ __half g_xn   [MM*DD];
static __device__ __half g_qkv  [MM*3*DD];
static __device__ __half g_o    [MM*DD];
static __device__ __half g_oproj[MM*DD];
static __device__ float  g_x    [MM*DD];
static __device__ __half g_ffnin[MM*FFN];
static __device__ float  g_Q    [HD*HD];
static __device__ __half g_w    [3*DD*DD];     // folded qkv weights (half)
static __device__ __half g_wo   [DD*DD];
static __device__ __half g_wg   [DD*DD];
static __device__ __half g_w12r [2*FFN*DD];
static __device__ __half g_w3r  [DD*FFN];

// ---------------- helpers ----------------
__device__ __forceinline__ void mma_f16(float c[4], uint32_t a0, uint32_t a1,
                                        uint32_t a2, uint32_t a3,
                                        uint32_t b0, uint32_t b1) {
    asm volatile(
        "mma.sync.aligned.m16n8k16.row.col.f32.f16.f16.f32 "
        "{%0,%1,%2,%3},{%4,%5,%6,%7},{%8,%9},{%0,%1,%2,%3};\n"
        : "+f"(c[0]), "+f"(c[1]), "+f"(c[2]), "+f"(c[3])
        : "r"(a0), "r"(a1), "r"(a2), "r"(a3), "r"(b0), "r"(b1));
}
__device__ __forceinline__ void ldsm4(uint32_t r[4], uint32_t addr) {
    asm volatile("ldmatrix.sync.aligned.m8n8.x4.shared.b16 {%0,%1,%2,%3}, [%4];"
        : "=r"(r[0]), "=r"(r[1]), "=r"(r[2]), "=r"(r[3]) : "r"(addr));
}
__device__ __forceinline__ void ldsm4t(uint32_t r[4], uint32_t addr) {
    asm volatile("ldmatrix.sync.aligned.m8n8.x4.trans.shared.b16 {%0,%1,%2,%3}, [%4];"
        : "=r"(r[0]), "=r"(r[1]), "=r"(r[2]), "=r"(r[3]) : "r"(addr));
}
__device__ __forceinline__ void cp16(uint32_t saddr, const void* gptr) {
    asm volatile("cp.async.cg.shared.global [%0], [%1], 16;\n" :: "r"(saddr), "l"(gptr));
}
#define CP_COMMIT() asm volatile("cp.async.commit_group;\n")
#define CP_WAIT1()  asm volatile("cp.async.wait_group 1;\n")
#define CP_WAIT0()  asm volatile("cp.async.wait_group 0;\n")
__device__ __forceinline__ uint32_t packh2(float lo, float hi) {
    uint32_t u;
    asm("cvt.rn.f16x2.f32 %0, %1, %2;" : "=r"(u) : "f"(hi), "f"(lo));
    return u;
}

// ---------------- float -> half convert pass (weights) ----------------
__global__ void cvth_k(const float* __restrict__ in, __half* __restrict__ out, int n4) {
    int i = blockIdx.x * blockDim.x + threadIdx.x;
    if (i >= n4) return;
    float4 v = ((const float4*)in)[i];
    uint2 o;
    o.x = packh2(v.x, v.y);
    o.y = packh2(v.z, v.w);
    ((uint2*)out)[i] = o;
}

// ---------------- rmsnorm (float in, half out) ----------------
__global__ void rmsnorm_k(const float* __restrict__ x, __half* __restrict__ y) {
    int row = blockIdx.x;
    const float4* xr = (const float4*)(x + (size_t)row * DD);
    int tid = threadIdx.x;
    float4 v = xr[tid];
    float s = v.x*v.x + v.y*v.y + v.z*v.z + v.w*v.w;
    #pragma unroll
    for (int w = 16; w > 0; w >>= 1) s += __shfl_xor_sync(0xffffffffu, s, w);
    __shared__ float red[8];
    __shared__ float tot;
    if ((tid & 31) == 0) red[tid >> 5] = s;
    __syncthreads();
    if (tid == 0) {
        float t = 0.f;
        #pragma unroll
        for (int i = 0; i < 8; i++) t += red[i];
        tot = t;
    }
    __syncthreads();
    float r = rsqrtf(tot / (float)DD + EPS_RMS);
    uint2 o;
    o.x = packh2(v.x*r, v.y*r);
    o.y = packh2(v.z*r, v.w*r);
    ((uint2*)(y + (size_t)row*DD))[tid] = o;
}

// ---------------- Householder product ----------------
__global__ void hh_k(const float* __restrict__ vs, float* __restrict__ Qout) {
    __shared__ float Q[HD][HD];
    __shared__ float v[HD];
    __shared__ float w[HD];
    __shared__ float cs;
    int tid = threadIdx.x;
    for (int idx = tid; idx < HD*HD; idx += 256)
        Q[idx / HD][idx % HD] = (idx / HD == idx % HD) ? 1.f : 0.f;
    __syncthreads();
    for (int r = 0; r < HD/2; r++) {
        if (tid < HD) v[tid] = vs[r*HD + tid];
        __syncthreads();
        if (tid == 0) {
            float n = 0.f;
            for (int i = 0; i < HD; i++) n += v[i]*v[i];
            cs = 2.f / (n + 1e-8f);
        }
        __syncthreads();
        if (tid < HD) {
            float s = 0.f;
            for (int i = 0; i < HD; i++) s += v[i] * Q[i][tid];
            w[tid] = s;
        }
        __syncthreads();
        for (int idx = tid; idx < HD*HD; idx += 256) {
            int i = idx / HD, j = idx % HD;
            Q[i][j] -= cs * v[i] * w[j];
        }
        __syncthreads();
    }
    for (int idx = tid; idx < HD*HD; idx += 256)
        Qout[idx] = Q[idx / HD][idx % HD];
}

// ---------------- fold Q into q,k weight rows: smem-tiled group GEMM ----------------
__global__ void __launch_bounds__(256) foldw2_k(const float* __restrict__ W,
                                                const float* __restrict__ Qm,
                                                __half* __restrict__ Wout) {
    __shared__ float Qs[64][64];
    __shared__ float Wt[64][128];
    int tid = threadIdx.x;
    int cc = blockIdx.x, gg = blockIdx.y;
    #pragma unroll
    for (int i = tid; i < 64*64; i += 256)
        ((float*)Qs)[i] = Qm[i];
    #pragma unroll
    for (int i = tid; i < 64*32; i += 256) {
        int j = i >> 5, c4 = i & 31;
        *(float4*)&Wt[j][c4*4] =
            *(const float4*)(W + (size_t)(gg*64 + j)*DD + cc*128 + c4*4);
    }
    __syncthreads();
    int rh = tid >> 7;
    int col = tid & 127;
    float acc[32] = {};
    #pragma unroll 4
    for (int j4 = 0; j4 < 16; j4++) {
        float wv0 = Wt[j4*4 + 0][col];
        float wv1 = Wt[j4*4 + 1][col];
        float wv2 = Wt[j4*4 + 2][col];
        float wv3 = Wt[j4*4 + 3][col];
        #pragma unroll
        for (int r = 0; r < 32; r++) {
            float4 q = *(const float4*)&Qs[rh*32 + r][j4*4];
            acc[r] += q.x*wv0 + q.y*wv1 + q.z*wv2 + q.w*wv3;
        }
    }
    #pragma unroll
    for (int r = 0; r < 32; r++)
        Wout[(size_t)(gg*64 + rh*32 + r)*DD + cc*128 + col] = __float2half_rn(acc[r]);
}

// ---------------- rope on q,k (vectorized half2; q pre-scaled by 1/8) ----------------
__global__ void rope_k(__half* __restrict__ qkv, const float* __restrict__ inv_freq,
                       const float* __restrict__ rope_pos) {
    int idx = blockIdx.x * 256 + threadIdx.x;   // MM*512 total
    int dp2 = idx & 15;
    int ph = (idx >> 4) & 31;
    int bs = idx >> 9;
    int s  = bs & (SS-1);
    float pos = rope_pos[2*s];
    int d0 = 2*dp2;
    float c0, s0, c1, s1;
    sincosf(pos * inv_freq[d0 & 15], &s0, &c0);
    sincosf(pos * inv_freq[(d0 + 1) & 15], &s1, &c1);
    size_t base = (size_t)bs*(3*DD) + (size_t)(ph>>4)*DD + (size_t)(ph&15)*HD;
    __half2 lo = *(__half2*)(qkv + base + d0);
    __half2 hi = *(__half2*)(qkv + base + d0 + 32);
    float t1a = __low2float(lo), t1b = __high2float(lo);
    float t2a = __low2float(hi), t2b = __high2float(hi);
    float o1a = t1a*c0 - t2a*s0, o2a = t2a*c0 + t1a*s0;
    float o1b = t1b*c1 - t2b*s1, o2b = t2b*c1 + t1b*s1;
    if (ph < 16) { o1a*=0.125f; o1b*=0.125f; o2a*=0.125f; o2b*=0.125f; }
    *(uint32_t*)(qkv + base + d0)      = packh2(o1a, o1b);
    *(uint32_t*)(qkv + base + d0 + 32) = packh2(o2a, o2b);
}

// ---------------- fp16 tensor-core GEMM, BK=64, 3-stage ring, 2 CTAs/SM ----------------
// Block 128x128, 8 warps 2(m)x4(n), warp tile 64x32. smem 110.6KB x2 = 221KB/SM.
// Per iter: wait1 (stage i landed) -> sync -> issue i+2 into buf((i+2)%3) -> commit
//           -> compute stage i.  Two copy-groups in flight during compute.
#define ASTR 72                            // halves per smem row (144 B, LDSM conflict-free)
#define STAGE_H (128*ASTR)                 // halves per stage per operand
#define TG_SMEM (3 * 2 * STAGE_H * 2)      // 110592 bytes
__global__ void __launch_bounds__(256, 2) tgemm_k(
        const __half* __restrict__ A, const __half* __restrict__ W,
        void* __restrict__ C, int M, int N, int K,
        const float* __restrict__ bias, const float* __restrict__ resid,
        const __half* __restrict__ gatein, int outHalf) {
    extern __shared__ __half smh[];
    __half* As = smh;
    __half* Bs = smh + 3*STAGE_H;
    uint32_t as_u32 = (uint32_t)__cvta_generic_to_shared(As);
    uint32_t bs_u32 = (uint32_t)__cvta_generic_to_shared(Bs);
    int tid = threadIdx.x;
    int lane = tid & 31, wid = tid >> 5;
    int wm = wid >> 2, wn = wid & 3;
    int g = lane >> 2, c = lane & 3;
    int m0 = blockIdx.y * 128, n0 = blockIdx.x * 128;
    int ar = lane & 15, ac = (lane >> 4) << 3;   // A-ldsm offsets
    int br = lane & 7,  bc = lane & 24;          // B-ldsm offsets

    float acc[4][4][4] = {};
    int nIter = K >> 6;

    // prologue: stages 0 and 1
    #pragma unroll
    for (int s = 0; s < 2; s++) {
        int k0 = s << 6;
        #pragma unroll
        for (int it = 0; it < 4; it++) {
            int idx = tid + it*256;
            int row = idx >> 3, ch = idx & 7;
            cp16(as_u32 + ((s*STAGE_H + row*ASTR + ch*8))*2, A + (size_t)(m0+row)*K + k0 + ch*8);
            cp16(bs_u32 + ((s*STAGE_H + row*ASTR + ch*8))*2, W + (size_t)(n0+row)*K + k0 + ch*8);
        }
        CP_COMMIT();
    }

    int buf = 0, nxt = 2;        // compute buffer, prefetch-target buffer
    for (int i = 0; i < nIter; i++) {
        CP_WAIT1();                   // stage i landed (this thread); i+1 may still fly
        __syncthreads();              // all threads' stage-i visible; buf nxt free
        if (i + 2 < nIter) {
            int k0 = (i + 2) << 6;
            #pragma unroll
            for (int it = 0; it < 4; it++) {
                int idx = tid + it*256;
                int row = idx >> 3, ch = idx & 7;
                cp16(as_u32 + ((nxt*STAGE_H + row*ASTR + ch*8))*2, A + (size_t)(m0+row)*K + k0 + ch*8);
                cp16(bs_u32 + ((nxt*STAGE_H + row*ASTR + ch*8))*2, W + (size_t)(n0+row)*K + k0 + ch*8);
            }
        }
        CP_COMMIT();
        uint32_t ab = as_u32 + buf*STAGE_H*2;
        uint32_t bb = bs_u32 + buf*STAGE_H*2;
        #pragma unroll
        for (int p = 0; p < 2; p++) {          // kk base 32p
            uint32_t bf[4][4];
            #pragma unroll
            for (int nf = 0; nf < 4; nf++) {
                int cb = wn*32 + nf*8;
                ldsm4(bf[nf], bb + ((cb + br)*ASTR + p*32 + bc)*2);
            }
            #pragma unroll
            for (int sub = 0; sub < 2; sub++) {
                int kk = p*32 + sub*16;
                #pragma unroll
                for (int mf = 0; mf < 4; mf++) {
                    int rb = wm*64 + mf*16;
                    uint32_t af[4];
                    ldsm4(af, ab + ((rb + ar)*ASTR + kk + ac)*2);
                    #pragma unroll
                    for (int nf = 0; nf < 4; nf++)
                        mma_f16(acc[mf][nf], af[0], af[1], af[2], af[3],
                                bf[nf][2*sub], bf[nf][2*sub+1]);
                }
            }
        }
        buf = (buf == 2) ? 0 : buf + 1;
        nxt = (nxt == 2) ? 0 : nxt + 1;
    }
    // epilogue
    #pragma unroll
    for (int mf = 0; mf < 4; mf++) {
        int r0 = m0 + wm*64 + mf*16 + g;
        #pragma unroll
        for (int nf = 0; nf < 4; nf++) {
            int col = n0 + wn*32 + nf*8 + 2*c;
            float v[2][2] = {{acc[mf][nf][0], acc[mf][nf][1]},
                             {acc[mf][nf][2], acc[mf][nf][3]}};
            if (bias) {
                float2 bv = *(const float2*)(bias + col);
                v[0][0]+=bv.x; v[0][1]+=bv.y; v[1][0]+=bv.x; v[1][1]+=bv.y;
            }
            if (gatein) {
                #pragma unroll
                for (int rr = 0; rr < 2; rr++) {
                    size_t off = (size_t)(r0 + 8*rr)*N + col;
                    float2 gi = __half22float2(*(const __half2*)(gatein + off));
                    float2 rs = *(const float2*)(resid + off);
                    v[rr][0] = rs.x + gi.x / (1.f + __expf(-v[rr][0]));
                    v[rr][1] = rs.y + gi.y / (1.f + __expf(-v[rr][1]));
                }
            } else if (resid) {
                #pragma unroll
                for (int rr = 0; rr < 2; rr++) {
                    float2 rs = *(const float2*)(resid + (size_t)(r0 + 8*rr)*N + col);
                    v[rr][0] += rs.x; v[rr][1] += rs.y;
                }
            }
            if (outHalf) {
                __half* Ch = (__half*)C;
                *(uint32_t*)(Ch + (size_t)r0*N + col)     = packh2(v[0][0], v[0][1]);
                *(uint32_t*)(Ch + (size_t)(r0+8)*N + col) = packh2(v[1][0], v[1][1]);
            } else {
                float* Cf = (float*)C;
                *(float2*)(Cf + (size_t)r0*N + col)     = make_float2(v[0][0], v[0][1]);
                *(float2*)(Cf + (size_t)(r0+8)*N + col) = make_float2(v[1][0], v[1][1]);
            }
        }
    }
}

// ---------------- fused w12 GEMM + SwiGLU (fp16), 3-stage ring ----------------
__global__ void __launch_bounds__(256, 2) gemm12_k(
        const __half* __restrict__ A, const __half* __restrict__ W12,
        __half* __restrict__ ffnin) {
    extern __shared__ __half smh[];
    __half* As = smh;
    __half* Bs = smh + 3*STAGE_H;
    uint32_t as_u32 = (uint32_t)__cvta_generic_to_shared(As);
    uint32_t bs_u32 = (uint32_t)__cvta_generic_to_shared(Bs);
    int tid = threadIdx.x;
    int lane = tid & 31, wid = tid >> 5;
    int wm = wid >> 2, wn = wid & 3;
    int g = lane >> 2, c = lane & 3;
    int m0 = blockIdx.y * 128, n0 = blockIdx.x * 64;
    int ar = lane & 15, ac = (lane >> 4) << 3;
    int br = lane & 7,  bc = lane & 24;
    const int K = DD;

    float acc[4][4][4] = {};   // [mf][nfi: hf*2+nf2][4]
    const int nIter = DD >> 6; // 16

    #pragma unroll
    for (int s = 0; s < 2; s++) {
        int k0 = s << 6;
        #pragma unroll
        for (int it = 0; it < 4; it++) {
            int idx = tid + it*256;
            int row = idx >> 3, ch = idx & 7;
            cp16(as_u32 + ((s*STAGE_H + row*ASTR + ch*8))*2, A + (size_t)(m0+row)*K + k0 + ch*8);
            int wr = (row < 64) ? (n0 + row) : (FFN + n0 + row - 64);
            cp16(bs_u32 + ((s*STAGE_H + row*ASTR + ch*8))*2, W12 + (size_t)wr*K + k0 + ch*8);
        }
        CP_COMMIT();
    }

    int buf = 0, nxt = 2;
    for (int i = 0; i < nIter; i++) {
        CP_WAIT1();
        __syncthreads();
        if (i + 2 < nIter) {
            int k0 = (i + 2) << 6;
            #pragma unroll
            for (int it = 0; it < 4; it++) {
                int idx = tid + it*256;
                int row = idx >> 3, ch = idx & 7;
                cp16(as_u32 + ((nxt*STAGE_H + row*ASTR + ch*8))*2, A + (size_t)(m0+row)*K + k0 + ch*8);
                int wr = (row < 64) ? (n0 + row) : (FFN + n0 + row - 64);
                cp16(bs_u32 + ((nxt*STAGE_H + row*ASTR + ch*8))*2, W12 + (size_t)wr*K + k0 + ch*8);
            }
        }
        CP_COMMIT();
        uint32_t ab = as_u32 + buf*STAGE_H*2;
        uint32_t bb = bs_u32 + buf*STAGE_H*2;
        #pragma unroll
        for (int p = 0; p < 2; p++) {
            uint32_t bf[4][4];
            #pragma unroll
            for (int nfi = 0; nfi < 4; nfi++) {
                int hf = nfi >> 1, nf2 = nfi & 1;
                int cb = hf*64 + wn*16 + nf2*8;
                ldsm4(bf[nfi], bb + ((cb + br)*ASTR + p*32 + bc)*2);
            }
            #pragma unroll
            for (int sub = 0; sub < 2; sub++) {
                int kk = p*32 + sub*16;
                #pragma unroll
                for (int mf = 0; mf < 4; mf++) {
                    int rb = wm*64 + mf*16;
                    uint32_t af[4];
                    ldsm4(af, ab + ((rb + ar)*ASTR + kk + ac)*2);
                    #pragma unroll
                    for (int nfi = 0; nfi < 4; nfi++)
                        mma_f16(acc[mf][nfi], af[0], af[1], af[2], af[3],
                                bf[nfi][2*sub], bf[nfi][2*sub+1]);
                }
            }
        }
        buf = (buf == 2) ? 0 : buf + 1;
        nxt = (nxt == 2) ? 0 : nxt + 1;
    }
    // epilogue: silu(x1) * x2 -> half
    #pragma unroll
    for (int mf = 0; mf < 4; mf++) {
        int r0 = m0 + wm*64 + mf*16 + g;
        #pragma unroll
        for (int nf2 = 0; nf2 < 2; nf2++) {
            int col = n0 + wn*16 + nf2*8 + 2*c;
            #pragma unroll
            for (int rr = 0; rr < 2; rr++) {
                float a0 = acc[mf][nf2][2*rr],   a1 = acc[mf][nf2][2*rr+1];
                float b0 = acc[mf][2+nf2][2*rr], b1 = acc[mf][2+nf2][2*rr+1];
                float o0 = (a0 / (1.f + __expf(-a0))) * b0;
                float o1 = (a1 / (1.f + __expf(-a1))) * b1;
                *(uint32_t*)(ffnin + (size_t)(r0 + 8*rr)*FFN + col) = packh2(o0, o1);
            }
        }
    }
}

// ---------------- fp16 flash attention: 2-stage KV ring, one barrier/tile, 2 CTAs/SM ----------------
#define QSTR 72
#define SMEM_FLASH ((128*QSTR + 2*64*QSTR + 2*64*QSTR) * 2)   // 55296 bytes

__global__ void __launch_bounds__(256, 2) flashm_k(const __half* __restrict__ qkv,
                                                   __half* __restrict__ o) {
    extern __shared__ __half smh[];
    __half* Qs = smh;
    __half* Ks = smh + 128*QSTR;
    __half* Vs = Ks + 2*64*QSTR;
    uint32_t qs_u32 = (uint32_t)__cvta_generic_to_shared(Qs);
    uint32_t ks_u32 = (uint32_t)__cvta_generic_to_shared(Ks);
    uint32_t vs_u32 = (uint32_t)__cvta_generic_to_shared(Vs);
    int tid = threadIdx.x;
    int lane = tid & 31, wid = tid >> 5;
    int g = lane >> 2, c = lane & 3;
    int ar = lane & 15, ac = (lane >> 4) << 3;
    int br = lane & 7,  bc = lane & 24;
    int qt = (int)gridDim.x - 1 - (int)blockIdx.x;   // longest first
    int q0 = qt * 128;
    int b = blockIdx.y >> 4, h = blockIdx.y & 15;
    size_t tok0 = (size_t)b * SS;
    int jmax = 2*qt + 1;    // >= 1 always

    // prologue: KV tile 0 into buf 0
    #pragma unroll
    for (int it = 0; it < 2; it++) {
        int idx = tid + it*256;
        int r = idx >> 3, ch = idx & 7;
        const __half* gk = qkv + (tok0 + r)*(size_t)(3*DD) + DD + h*HD + ch*8;
        cp16(ks_u32 + (r*QSTR + ch*8)*2, gk);
        cp16(vs_u32 + (r*QSTR + ch*8)*2, gk + DD);
    }
    CP_COMMIT();
    // stage Q (128x64 halves)
    #pragma unroll
    for (int it = 0; it < 4; it++) {
        int idx = tid + it*256;
        int r = idx >> 3, ch = idx & 7;
        uint4 v = *(const uint4*)(qkv + (tok0 + q0 + r)*(size_t)(3*DD) + h*HD + ch*8);
        *(uint4*)(Qs + r*QSTR + ch*8) = v;
    }
    __syncthreads();
    int qrow = q0 + wid*16;
    uint32_t qf[4][4];
    #pragma unroll
    for (int kg = 0; kg < 4; kg++)
        ldsm4(qf[kg], qs_u32 + ((wid*16 + ar)*QSTR + kg*16 + ac)*2);

    float oacc[8][4];
    #pragma unroll
    for (int nf = 0; nf < 8; nf++)
        #pragma unroll
        for (int i = 0; i < 4; i++) oacc[nf][i] = 0.f;
    float m0r = -1e30f, m1r = -1e30f, l0r = 0.f, l1r = 0.f;

    for (int jt = 0; jt <= jmax; jt++) {
        int j0 = jt * 64;
        int buf = jt & 1;
        CP_WAIT0();                 // tile jt landed (this thread)
        __syncthreads();            // tile jt visible to all; other buf free (jt-1 consumed)
        if (jt < jmax) {            // prefetch tile jt+1 into other buf
            int nb = (jt + 1) & 1;
            int nj0 = (jt + 1) * 64;
            #pragma unroll
            for (int it = 0; it < 2; it++) {
                int idx = tid + it*256;
                int r = idx >> 3, ch = idx & 7;
                const __half* gk = qkv + (tok0 + nj0 + r)*(size_t)(3*DD) + DD + h*HD + ch*8;
                cp16(ks_u32 + ((nb*64 + r)*QSTR + ch*8)*2, gk);
                cp16(vs_u32 + ((nb*64 + r)*QSTR + ch*8)*2, gk + DD);
            }
        }
        CP_COMMIT();
        uint32_t kb = ks_u32 + buf*64*QSTR*2;
        uint32_t vb = vs_u32 + buf*64*QSTR*2;
        if (j0 <= qrow + 15) {
            // S = Q K^T (16x64 per warp)
            float sacc[8][4];
            #pragma unroll
            for (int nf = 0; nf < 8; nf++)
                #pragma unroll
                for (int i = 0; i < 4; i++) sacc[nf][i] = 0.f;
            #pragma unroll
            for (int p = 0; p < 2; p++) {
                #pragma unroll
                for (int nf = 0; nf < 8; nf++) {
                    uint32_t kf[4];
                    ldsm4(kf, kb + ((nf*8 + br)*QSTR + p*32 + bc)*2);
                    mma_f16(sacc[nf], qf[2*p][0], qf[2*p][1], qf[2*p][2], qf[2*p][3], kf[0], kf[1]);
                    mma_f16(sacc[nf], qf[2*p+1][0], qf[2*p+1][1], qf[2*p+1][2], qf[2*p+1][3], kf[2], kf[3]);
                }
            }
            // causal mask near the diagonal
            if (j0 + 63 > qrow) {
                #pragma unroll
                for (int nf = 0; nf < 8; nf++) {
                    int col = j0 + nf*8 + 2*c;
                    if (col     > qrow + g)     sacc[nf][0] = -1e30f;
                    if (col + 1 > qrow + g)     sacc[nf][1] = -1e30f;
                    if (col     > qrow + 8 + g) sacc[nf][2] = -1e30f;
                    if (col + 1 > qrow + 8 + g) sacc[nf][3] = -1e30f;
                }
            }
            // online softmax (rows live in 4 lanes sharing g)
            float mx0 = -1e30f, mx1 = -1e30f;
            #pragma unroll
            for (int nf = 0; nf < 8; nf++) {
                mx0 = fmaxf(mx0, fmaxf(sacc[nf][0], sacc[nf][1]));
                mx1 = fmaxf(mx1, fmaxf(sacc[nf][2], sacc[nf][3]));
            }
            mx0 = fmaxf(mx0, __shfl_xor_sync(0xffffffffu, mx0, 1));
            mx0 = fmaxf(mx0, __shfl_xor_sync(0xffffffffu, mx0, 2));
            mx1 = fmaxf(mx1, __shfl_xor_sync(0xffffffffu, mx1, 1));
            mx1 = fmaxf(mx1, __shfl_xor_sync(0xffffffffu, mx1, 2));
            float nm0 = fmaxf(m0r, mx0), nm1 = fmaxf(m1r, mx1);
            float al0 = __expf(m0r - nm0), al1 = __expf(m1r - nm1);
            float sum0 = 0.f, sum1 = 0.f;
            #pragma unroll
            for (int nf = 0; nf < 8; nf++) {
                float p0 = __expf(sacc[nf][0] - nm0);
                float p1 = __expf(sacc[nf][1] - nm0);
                float p2 = __expf(sacc[nf][2] - nm1);
                float p3 = __expf(sacc[nf][3] - nm1);
                sacc[nf][0] = p0; sacc[nf][1] = p1; sacc[nf][2] = p2; sacc[nf][3] = p3;
                sum0 += p0 + p1; sum1 += p2 + p3;
            }
            sum0 += __shfl_xor_sync(0xffffffffu, sum0, 1);
            sum0 += __shfl_xor_sync(0xffffffffu, sum0, 2);
            sum1 += __shfl_xor_sync(0xffffffffu, sum1, 1);
            sum1 += __shfl_xor_sync(0xffffffffu, sum1, 2);
            l0r = l0r*al0 + sum0; l1r = l1r*al1 + sum1;
            m0r = nm0; m1r = nm1;
            // P fragments stay in registers (C layout == A layout)
            uint32_t pa[4][4];
            #pragma unroll
            for (int ks = 0; ks < 4; ks++) {
                pa[ks][0] = packh2(sacc[2*ks][0],   sacc[2*ks][1]);
                pa[ks][1] = packh2(sacc[2*ks][2],   sacc[2*ks][3]);
                pa[ks][2] = packh2(sacc[2*ks+1][0], sacc[2*ks+1][1]);
                pa[ks][3] = packh2(sacc[2*ks+1][2], sacc[2*ks+1][3]);
            }
            // rescale O
            #pragma unroll
            for (int nf = 0; nf < 8; nf++) {
                oacc[nf][0] *= al0; oacc[nf][1] *= al0;
                oacc[nf][2] *= al1; oacc[nf][3] *= al1;
            }
            // O += P @ V  (V via trans-ldmatrix)
            #pragma unroll
            for (int p = 0; p < 2; p++) {
                #pragma unroll
                for (int nf = 0; nf < 8; nf++) {
                    uint32_t vf[4];
                    ldsm4t(vf, vb + ((p*32 + lane)*QSTR + nf*8)*2);
                    mma_f16(oacc[nf], pa[2*p][0], pa[2*p][1], pa[2*p][2], pa[2*p][3], vf[0], vf[1]);
                    mma_f16(oacc[nf], pa[2*p+1][0], pa[2*p+1][1], pa[2*p+1][2], pa[2*p+1][3], vf[2], vf[3]);
                }
            }
        }
    }
    // epilogue -> half
    float inv0 = 1.f / l0r, inv1 = 1.f / l1r;
    #pragma unroll
    for (int nf = 0; nf < 8; nf++) {
        int col = h*HD + nf*8 + 2*c;
        size_t r0 = (tok0 + qrow + g    )*(size_t)DD + col;
        size_t r1 = (tok0 + qrow + 8 + g)*(size_t)DD + col;
        *(uint32_t*)(o + r0) = packh2(oacc[nf][0]*inv0, oacc[nf][1]*inv0);
        *(uint32_t*)(o + r1) = packh2(oacc[nf][2]*inv1, oacc[nf][3]*inv1);
    }
}

// ---------------- launch ----------------
extern "C" void kernel_launch(void* const* d_in, const int* in_sizes, int n_in,
                              void* d_out, int out_size) {
    const float* x        = (const float*)d_in[0];
    const float* qkv_w    = (const float*)d_in[2];
    const float* out_w    = (const float*)d_in[3];
    const float* gate_w   = (const float*)d_in[4];
    const float* gate_b   = (const float*)d_in[5];
    const float* w12      = (const float*)d_in[6];
    const float* w3       = (const float*)d_in[7];
    const float* hh_vs    = (const float*)d_in[8];
    const float* inv_freq = (const float*)d_in[9];
    const float* rope_pos = (const float*)d_in[10];
    float* out = (float*)d_out;

    __half *xn, *qkv, *o_, *oproj, *ffnin, *wf, *wo, *wg, *w12r, *w3r;
    float *x_, *Qm;
    cudaGetSymbolAddress((void**)&xn,    g_xn);
    cudaGetSymbolAddress((void**)&qkv,   g_qkv);
    cudaGetSymbolAddress((void**)&o_,    g_o);
    cudaGetSymbolAddress((void**)&oproj, g_oproj);
    cudaGetSymbolAddress((void**)&x_,    g_x);
    cudaGetSymbolAddress((void**)&ffnin, g_ffnin);
    cudaGetSymbolAddress((void**)&Qm,    g_Q);
    cudaGetSymbolAddress((void**)&wf,    g_w);
    cudaGetSymbolAddress((void**)&wo,    g_wo);
    cudaGetSymbolAddress((void**)&wg,    g_wg);
    cudaGetSymbolAddress((void**)&w12r,  g_w12r);
    cudaGetSymbolAddress((void**)&w3r,   g_w3r);

    static bool attr_set = false;
    if (!attr_set) {
        cudaFuncSetAttribute(flashm_k, cudaFuncAttributeMaxDynamicSharedMemorySize, SMEM_FLASH);
        cudaFuncSetAttribute(tgemm_k, cudaFuncAttributeMaxDynamicSharedMemorySize, TG_SMEM);
        cudaFuncSetAttribute(gemm12_k, cudaFuncAttributeMaxDynamicSharedMemorySize, TG_SMEM);
        attr_set = true;
    }

    rmsnorm_k<<<MM, 256>>>(x, xn);
    hh_k<<<1, 256>>>(hh_vs, Qm);
    // fold Q into q,k rows (smem-tiled); v rows are a plain convert
    foldw2_k<<<dim3(8, 32), 256>>>(qkv_w, Qm, wf);
    cvth_k<<<(DD*DD/4 + 255)/256, 256>>>(qkv_w + 2*DD*DD, wf + 2*DD*DD, DD*DD/4);
    tgemm_k<<<dim3((3*DD)/128, MM/128), 256, TG_SMEM>>>(xn, wf, qkv, MM, 3*DD, DD,
                                                        nullptr, nullptr, nullptr, 1);
    rope_k<<<(MM*512)/256, 256>>>(qkv, inv_freq, rope_pos);
    flashm_k<<<dim3(SS/128, BB*HH), 256, SMEM_FLASH>>>(qkv, o_);
    // weight conversions (needed only from here on)
    cvth_k<<<(DD*DD/4 + 255)/256, 256>>>(out_w, wo, DD*DD/4);
    cvth_k<<<(DD*DD/4 + 255)/256, 256>>>(gate_w, wg, DD*DD/4);
    tgemm_k<<<dim3(DD/128, MM/128), 256, TG_SMEM>>>(o_, wo, oproj, MM, DD, DD,
                                                    nullptr, nullptr, nullptr, 1);
    // gate GEMM fused: x_ = x + oproj * sigmoid(oproj@gate_w^T + b)   (fp32 out)
    tgemm_k<<<dim3(DD/128, MM/128), 256, TG_SMEM>>>(oproj, wg, x_, MM, DD, DD,
                                                    gate_b, x, oproj, 0);
    rmsnorm_k<<<MM, 256>>>(x_, xn);
    cvth_k<<<(2*FFN*DD/4 + 255)/256, 256>>>(w12, w12r, 2*FFN*DD/4);
    gemm12_k<<<dim3(FFN/64, MM/128), 256, TG_SMEM>>>(xn, w12r, ffnin);
    cvth_k<<<(DD*FFN/4 + 255)/256, 256>>>(w3, w3r, DD*FFN/4);
    tgemm_k<<<dim3(DD/128, MM/128), 256, TG_SMEM>>>(ffnin, w3r, out, MM, DD, FFN,
                                                    nullptr, x_, nullptr, 0);
}

// round 17
// speedup vs baseline: 1.0330x; 1.0330x over previous
#include <cuda_runtime.h>
#include <cuda_fp16.h>
#include <math.h>
#include <stdint.h>

// Problem constants
#define BB 2
#define SS 2048
#define DD 1024
#define HH 16
#define HD 64
#define FFN 4096
#define MM (BB*SS)          // 4096 rows
#define EPS_RMS 1.1920929e-07f

// ---------------- scratch (device globals; allocation-free) ----------------
static __device__ __half g_xn   [MM*DD];
static __device__ __half g_qkv  [MM*3*DD];
static __device__ __half g_o    [MM*DD];
static __device__ __half g_oproj[MM*DD];
static __device__ float  g_x    [MM*DD];
static __device__ __half g_ffnin[MM*FFN];
static __device__ float  g_Q    [HD*HD];
static __device__ __half g_w    [3*DD*DD];     // folded qkv weights (half)
static __device__ __half g_wo   [DD*DD];
static __device__ __half g_wg   [DD*DD];
static __device__ __half g_w12r [2*FFN*DD];
static __device__ __half g_w3r  [DD*FFN];

// ---------------- helpers ----------------
__device__ __forceinline__ void mma_f16(float c[4], uint32_t a0, uint32_t a1,
                                        uint32_t a2, uint32_t a3,
                                        uint32_t b0, uint32_t b1) {
    asm volatile(
        "mma.sync.aligned.m16n8k16.row.col.f32.f16.f16.f32 "
        "{%0,%1,%2,%3},{%4,%5,%6,%7},{%8,%9},{%0,%1,%2,%3};\n"
        : "+f"(c[0]), "+f"(c[1]), "+f"(c[2]), "+f"(c[3])
        : "r"(a0), "r"(a1), "r"(a2), "r"(a3), "r"(b0), "r"(b1));
}
__device__ __forceinline__ void ldsm4(uint32_t r[4], uint32_t addr) {
    asm volatile("ldmatrix.sync.aligned.m8n8.x4.shared.b16 {%0,%1,%2,%3}, [%4];"
        : "=r"(r[0]), "=r"(r[1]), "=r"(r[2]), "=r"(r[3]) : "r"(addr));
}
__device__ __forceinline__ void ldsm4t(uint32_t r[4], uint32_t addr) {
    asm volatile("ldmatrix.sync.aligned.m8n8.x4.trans.shared.b16 {%0,%1,%2,%3}, [%4];"
        : "=r"(r[0]), "=r"(r[1]), "=r"(r[2]), "=r"(r[3]) : "r"(addr));
}
__device__ __forceinline__ void cp16(uint32_t saddr, const void* gptr) {
    asm volatile("cp.async.cg.shared.global [%0], [%1], 16;\n" :: "r"(saddr), "l"(gptr));
}
#define CP_COMMIT() asm volatile("cp.async.commit_group;\n")
#define CP_WAIT1()  asm volatile("cp.async.wait_group 1;\n")
#define CP_WAIT0()  asm volatile("cp.async.wait_group 0;\n")
__device__ __forceinline__ uint32_t packh2(float lo, float hi) {
    uint32_t u;
    asm("cvt.rn.f16x2.f32 %0, %1, %2;" : "=r"(u) : "f"(hi), "f"(lo));
    return u;
}

// ---------------- float -> half convert pass (weights) ----------------
__global__ void cvth_k(const float* __restrict__ in, __half* __restrict__ out, int n4) {
    int i = blockIdx.x * blockDim.x + threadIdx.x;
    if (i >= n4) return;
    float4 v = ((const float4*)in)[i];
    uint2 o;
    o.x = packh2(v.x, v.y);
    o.y = packh2(v.z, v.w);
    ((uint2*)out)[i] = o;
}

// ---------------- rmsnorm (float in, half out) ----------------
__global__ void rmsnorm_k(const float* __restrict__ x, __half* __restrict__ y) {
    int row = blockIdx.x;
    const float4* xr = (const float4*)(x + (size_t)row * DD);
    int tid = threadIdx.x;
    float4 v = xr[tid];
    float s = v.x*v.x + v.y*v.y + v.z*v.z + v.w*v.w;
    #pragma unroll
    for (int w = 16; w > 0; w >>= 1) s += __shfl_xor_sync(0xffffffffu, s, w);
    __shared__ float red[8];
    __shared__ float tot;
    if ((tid & 31) == 0) red[tid >> 5] = s;
    __syncthreads();
    if (tid == 0) {
        float t = 0.f;
        #pragma unroll
        for (int i = 0; i < 8; i++) t += red[i];
        tot = t;
    }
    __syncthreads();
    float r = rsqrtf(tot / (float)DD + EPS_RMS);
    uint2 o;
    o.x = packh2(v.x*r, v.y*r);
    o.y = packh2(v.z*r, v.w*r);
    ((uint2*)(y + (size_t)row*DD))[tid] = o;
}

// ---------------- Householder product ----------------
__global__ void hh_k(const float* __restrict__ vs, float* __restrict__ Qout) {
    __shared__ float Q[HD][HD];
    __shared__ float v[HD];
    __shared__ float w[HD];
    __shared__ float cs;
    int tid = threadIdx.x;
    for (int idx = tid; idx < HD*HD; idx += 256)
        Q[idx / HD][idx % HD] = (idx / HD == idx % HD) ? 1.f : 0.f;
    __syncthreads();
    for (int r = 0; r < HD/2; r++) {
        if (tid < HD) v[tid] = vs[r*HD + tid];
        __syncthreads();
        if (tid == 0) {
            float n = 0.f;
            for (int i = 0; i < HD; i++) n += v[i]*v[i];
            cs = 2.f / (n + 1e-8f);
        }
        __syncthreads();
        if (tid < HD) {
            float s = 0.f;
            for (int i = 0; i < HD; i++) s += v[i] * Q[i][tid];
            w[tid] = s;
        }
        __syncthreads();
        for (int idx = tid; idx < HD*HD; idx += 256) {
            int i = idx / HD, j = idx % HD;
            Q[i][j] -= cs * v[i] * w[j];
        }
        __syncthreads();
    }
    for (int idx = tid; idx < HD*HD; idx += 256)
        Qout[idx] = Q[idx / HD][idx % HD];
}

// ---------------- fold Q into q,k weight rows: smem-tiled group GEMM ----------------
__global__ void __launch_bounds__(256) foldw2_k(const float* __restrict__ W,
                                                const float* __restrict__ Qm,
                                                __half* __restrict__ Wout) {
    __shared__ float Qs[64][64];
    __shared__ float Wt[64][128];
    int tid = threadIdx.x;
    int cc = blockIdx.x, gg = blockIdx.y;
    #pragma unroll
    for (int i = tid; i < 64*64; i += 256)
        ((float*)Qs)[i] = Qm[i];
    #pragma unroll
    for (int i = tid; i < 64*32; i += 256) {
        int j = i >> 5, c4 = i & 31;
        *(float4*)&Wt[j][c4*4] =
            *(const float4*)(W + (size_t)(gg*64 + j)*DD + cc*128 + c4*4);
    }
    __syncthreads();
    int rh = tid >> 7;
    int col = tid & 127;
    float acc[32] = {};
    #pragma unroll 4
    for (int j4 = 0; j4 < 16; j4++) {
        float wv0 = Wt[j4*4 + 0][col];
        float wv1 = Wt[j4*4 + 1][col];
        float wv2 = Wt[j4*4 + 2][col];
        float wv3 = Wt[j4*4 + 3][col];
        #pragma unroll
        for (int r = 0; r < 32; r++) {
            float4 q = *(const float4*)&Qs[rh*32 + r][j4*4];
            acc[r] += q.x*wv0 + q.y*wv1 + q.z*wv2 + q.w*wv3;
        }
    }
    #pragma unroll
    for (int r = 0; r < 32; r++)
        Wout[(size_t)(gg*64 + rh*32 + r)*DD + cc*128 + col] = __float2half_rn(acc[r]);
}

// ---------------- rope on q,k (vectorized half2; q pre-scaled by 1/8) ----------------
__global__ void rope_k(__half* __restrict__ qkv, const float* __restrict__ inv_freq,
                       const float* __restrict__ rope_pos) {
    int idx = blockIdx.x * 256 + threadIdx.x;   // MM*512 total
    int dp2 = idx & 15;
    int ph = (idx >> 4) & 31;
    int bs = idx >> 9;
    int s  = bs & (SS-1);
    float pos = rope_pos[2*s];
    int d0 = 2*dp2;
    float c0, s0, c1, s1;
    sincosf(pos * inv_freq[d0 & 15], &s0, &c0);
    sincosf(pos * inv_freq[(d0 + 1) & 15], &s1, &c1);
    size_t base = (size_t)bs*(3*DD) + (size_t)(ph>>4)*DD + (size_t)(ph&15)*HD;
    __half2 lo = *(__half2*)(qkv + base + d0);
    __half2 hi = *(__half2*)(qkv + base + d0 + 32);
    float t1a = __low2float(lo), t1b = __high2float(lo);
    float t2a = __low2float(hi), t2b = __high2float(hi);
    float o1a = t1a*c0 - t2a*s0, o2a = t2a*c0 + t1a*s0;
    float o1b = t1b*c1 - t2b*s1, o2b = t2b*c1 + t1b*s1;
    if (ph < 16) { o1a*=0.125f; o1b*=0.125f; o2a*=0.125f; o2b*=0.125f; }
    *(uint32_t*)(qkv + base + d0)      = packh2(o1a, o1b);
    *(uint32_t*)(qkv + base + d0 + 32) = packh2(o2a, o2b);
}

// ---------------- fp16 tensor-core GEMM, BK=64, 2-stage ring, one barrier/iter ----------------
// Block 128x128, 8 warps 2(m)x4(n), warp tile 64x32. 2 CTAs/SM.
#define ASTR 72                            // halves per smem row (144 B, LDSM conflict-free)
#define STAGE_H (128*ASTR)                 // halves per stage per operand
#define TG_SMEM (2 * 2 * STAGE_H * 2)      // 73728 bytes
__global__ void __launch_bounds__(256, 2) tgemm_k(
        const __half* __restrict__ A, const __half* __restrict__ W,
        void* __restrict__ C, int M, int N, int K,
        const float* __restrict__ bias, const float* __restrict__ resid,
        const __half* __restrict__ gatein, int outHalf) {
    extern __shared__ __half smh[];
    __half* As = smh;
    __half* Bs = smh + 2*STAGE_H;
    uint32_t as_u32 = (uint32_t)__cvta_generic_to_shared(As);
    uint32_t bs_u32 = (uint32_t)__cvta_generic_to_shared(Bs);
    int tid = threadIdx.x;
    int lane = tid & 31, wid = tid >> 5;
    int wm = wid >> 2, wn = wid & 3;
    int g = lane >> 2, c = lane & 3;
    int m0 = blockIdx.y * 128, n0 = blockIdx.x * 128;
    int ar = lane & 15, ac = (lane >> 4) << 3;   // A-ldsm offsets
    int br = lane & 7,  bc = lane & 24;          // B-ldsm offsets

    float acc[4][4][4] = {};
    int nIter = K >> 6;

    // prologue: stage 0
    #pragma unroll
    for (int it = 0; it < 4; it++) {
        int idx = tid + it*256;
        int row = idx >> 3, ch = idx & 7;
        cp16(as_u32 + ((row*ASTR + ch*8))*2, A + (size_t)(m0+row)*K + ch*8);
        cp16(bs_u32 + ((row*ASTR + ch*8))*2, W + (size_t)(n0+row)*K + ch*8);
    }
    CP_COMMIT();

    for (int i = 0; i < nIter; i++) {
        int buf = i & 1;
        CP_WAIT0();                   // stage i landed (this thread)
        __syncthreads();              // all threads' stage-i visible; other buf free
        if (i + 1 < nIter) {
            int nb = (i + 1) & 1;
            int k0 = (i + 1) << 6;
            #pragma unroll
            for (int it = 0; it < 4; it++) {
                int idx = tid + it*256;
                int row = idx >> 3, ch = idx & 7;
                cp16(as_u32 + ((nb*STAGE_H + row*ASTR + ch*8))*2, A + (size_t)(m0+row)*K + k0 + ch*8);
                cp16(bs_u32 + ((nb*STAGE_H + row*ASTR + ch*8))*2, W + (size_t)(n0+row)*K + k0 + ch*8);
            }
        }
        CP_COMMIT();
        uint32_t ab = as_u32 + buf*STAGE_H*2;
        uint32_t bb = bs_u32 + buf*STAGE_H*2;
        #pragma unroll
        for (int p = 0; p < 2; p++) {          // kk base 32p
            uint32_t bf[4][4];
            #pragma unroll
            for (int nf = 0; nf < 4; nf++) {
                int cb = wn*32 + nf*8;
                ldsm4(bf[nf], bb + ((cb + br)*ASTR + p*32 + bc)*2);
            }
            #pragma unroll
            for (int sub = 0; sub < 2; sub++) {
                int kk = p*32 + sub*16;
                #pragma unroll
                for (int mf = 0; mf < 4; mf++) {
                    int rb = wm*64 + mf*16;
                    uint32_t af[4];
                    ldsm4(af, ab + ((rb + ar)*ASTR + kk + ac)*2);
                    #pragma unroll
                    for (int nf = 0; nf < 4; nf++)
                        mma_f16(acc[mf][nf], af[0], af[1], af[2], af[3],
                                bf[nf][2*sub], bf[nf][2*sub+1]);
                }
            }
        }
    }
    // epilogue
    #pragma unroll
    for (int mf = 0; mf < 4; mf++) {
        int r0 = m0 + wm*64 + mf*16 + g;
        #pragma unroll
        for (int nf = 0; nf < 4; nf++) {
            int col = n0 + wn*32 + nf*8 + 2*c;
            float v[2][2] = {{acc[mf][nf][0], acc[mf][nf][1]},
                             {acc[mf][nf][2], acc[mf][nf][3]}};
            if (bias) {
                float2 bv = *(const float2*)(bias + col);
                v[0][0]+=bv.x; v[0][1]+=bv.y; v[1][0]+=bv.x; v[1][1]+=bv.y;
            }
            if (gatein) {
                #pragma unroll
                for (int rr = 0; rr < 2; rr++) {
                    size_t off = (size_t)(r0 + 8*rr)*N + col;
                    float2 gi = __half22float2(*(const __half2*)(gatein + off));
                    float2 rs = *(const float2*)(resid + off);
                    v[rr][0] = rs.x + gi.x / (1.f + __expf(-v[rr][0]));
                    v[rr][1] = rs.y + gi.y / (1.f + __expf(-v[rr][1]));
                }
            } else if (resid) {
                #pragma unroll
                for (int rr = 0; rr < 2; rr++) {
                    float2 rs = *(const float2*)(resid + (size_t)(r0 + 8*rr)*N + col);
                    v[rr][0] += rs.x; v[rr][1] += rs.y;
                }
            }
            if (outHalf) {
                __half* Ch = (__half*)C;
                *(uint32_t*)(Ch + (size_t)r0*N + col)     = packh2(v[0][0], v[0][1]);
                *(uint32_t*)(Ch + (size_t)(r0+8)*N + col) = packh2(v[1][0], v[1][1]);
            } else {
                float* Cf = (float*)C;
                *(float2*)(Cf + (size_t)r0*N + col)     = make_float2(v[0][0], v[0][1]);
                *(float2*)(Cf + (size_t)(r0+8)*N + col) = make_float2(v[1][0], v[1][1]);
            }
        }
    }
}

// ---------------- fused w12 GEMM + SwiGLU (fp16), 2-stage ring ----------------
__global__ void __launch_bounds__(256, 2) gemm12_k(
        const __half* __restrict__ A, const __half* __restrict__ W12,
        __half* __restrict__ ffnin) {
    extern __shared__ __half smh[];
    __half* As = smh;
    __half* Bs = smh + 2*STAGE_H;
    uint32_t as_u32 = (uint32_t)__cvta_generic_to_shared(As);
    uint32_t bs_u32 = (uint32_t)__cvta_generic_to_shared(Bs);
    int tid = threadIdx.x;
    int lane = tid & 31, wid = tid >> 5;
    int wm = wid >> 2, wn = wid & 3;
    int g = lane >> 2, c = lane & 3;
    int m0 = blockIdx.y * 128, n0 = blockIdx.x * 64;
    int ar = lane & 15, ac = (lane >> 4) << 3;
    int br = lane & 7,  bc = lane & 24;
    const int K = DD;

    float acc[4][4][4] = {};   // [mf][nfi: hf*2+nf2][4]
    const int nIter = DD >> 6; // 16

    #pragma unroll
    for (int it = 0; it < 4; it++) {
        int idx = tid + it*256;
        int row = idx >> 3, ch = idx & 7;
        cp16(as_u32 + ((row*ASTR + ch*8))*2, A + (size_t)(m0+row)*K + ch*8);
        int wr = (row < 64) ? (n0 + row) : (FFN + n0 + row - 64);
        cp16(bs_u32 + ((row*ASTR + ch*8))*2, W12 + (size_t)wr*K + ch*8);
    }
    CP_COMMIT();

    for (int i = 0; i < nIter; i++) {
        int buf = i & 1;
        CP_WAIT0();
        __syncthreads();
        if (i + 1 < nIter) {
            int nb = (i + 1) & 1;
            int k0 = (i + 1) << 6;
            #pragma unroll
            for (int it = 0; it < 4; it++) {
                int idx = tid + it*256;
                int row = idx >> 3, ch = idx & 7;
                cp16(as_u32 + ((nb*STAGE_H + row*ASTR + ch*8))*2, A + (size_t)(m0+row)*K + k0 + ch*8);
                int wr = (row < 64) ? (n0 + row) : (FFN + n0 + row - 64);
                cp16(bs_u32 + ((nb*STAGE_H + row*ASTR + ch*8))*2, W12 + (size_t)wr*K + k0 + ch*8);
            }
        }
        CP_COMMIT();
        uint32_t ab = as_u32 + buf*STAGE_H*2;
        uint32_t bb = bs_u32 + buf*STAGE_H*2;
        #pragma unroll
        for (int p = 0; p < 2; p++) {
            uint32_t bf[4][4];
            #pragma unroll
            for (int nfi = 0; nfi < 4; nfi++) {
                int hf = nfi >> 1, nf2 = nfi & 1;
                int cb = hf*64 + wn*16 + nf2*8;
                ldsm4(bf[nfi], bb + ((cb + br)*ASTR + p*32 + bc)*2);
            }
            #pragma unroll
            for (int sub = 0; sub < 2; sub++) {
                int kk = p*32 + sub*16;
                #pragma unroll
                for (int mf = 0; mf < 4; mf++) {
                    int rb = wm*64 + mf*16;
                    uint32_t af[4];
                    ldsm4(af, ab + ((rb + ar)*ASTR + kk + ac)*2);
                    #pragma unroll
                    for (int nfi = 0; nfi < 4; nfi++)
                        mma_f16(acc[mf][nfi], af[0], af[1], af[2], af[3],
                                bf[nfi][2*sub], bf[nfi][2*sub+1]);
                }
            }
        }
    }
    // epilogue: silu(x1) * x2 -> half
    #pragma unroll
    for (int mf = 0; mf < 4; mf++) {
        int r0 = m0 + wm*64 + mf*16 + g;
        #pragma unroll
        for (int nf2 = 0; nf2 < 2; nf2++) {
            int col = n0 + wn*16 + nf2*8 + 2*c;
            #pragma unroll
            for (int rr = 0; rr < 2; rr++) {
                float a0 = acc[mf][nf2][2*rr],   a1 = acc[mf][nf2][2*rr+1];
                float b0 = acc[mf][2+nf2][2*rr], b1 = acc[mf][2+nf2][2*rr+1];
                float o0 = (a0 / (1.f + __expf(-a0))) * b0;
                float o1 = (a1 / (1.f + __expf(-a1))) * b1;
                *(uint32_t*)(ffnin + (size_t)(r0 + 8*rr)*FFN + col) = packh2(o0, o1);
            }
        }
    }
}

// ---------------- fp16 flash attention: 2-stage KV ring, one barrier/tile, 2 CTAs/SM ----------------
#define QSTR 72
#define SMEM_FLASH ((128*QSTR + 2*64*QSTR + 2*64*QSTR) * 2)   // 55296 bytes

__global__ void __launch_bounds__(256, 2) flashm_k(const __half* __restrict__ qkv,
                                                   __half* __restrict__ o) {
    extern __shared__ __half smh[];
    __half* Qs = smh;
    __half* Ks = smh + 128*QSTR;
    __half* Vs = Ks + 2*64*QSTR;
    uint32_t qs_u32 = (uint32_t)__cvta_generic_to_shared(Qs);
    uint32_t ks_u32 = (uint32_t)__cvta_generic_to_shared(Ks);
    uint32_t vs_u32 = (uint32_t)__cvta_generic_to_shared(Vs);
    int tid = threadIdx.x;
    int lane = tid & 31, wid = tid >> 5;
    int g = lane >> 2, c = lane & 3;
    int ar = lane & 15, ac = (lane >> 4) << 3;
    int br = lane & 7,  bc = lane & 24;
    int qt = (int)gridDim.x - 1 - (int)blockIdx.x;   // longest first
    int q0 = qt * 128;
    int b = blockIdx.y >> 4, h = blockIdx.y & 15;
    size_t tok0 = (size_t)b * SS;
    int jmax = 2*qt + 1;    // >= 1 always

    // prologue: KV tile 0 into buf 0
    #pragma unroll
    for (int it = 0; it < 2; it++) {
        int idx = tid + it*256;
        int r = idx >> 3, ch = idx & 7;
        const __half* gk = qkv + (tok0 + r)*(size_t)(3*DD) + DD + h*HD + ch*8;
        cp16(ks_u32 + (r*QSTR + ch*8)*2, gk);
        cp16(vs_u32 + (r*QSTR + ch*8)*2, gk + DD);
    }
    CP_COMMIT();
    // stage Q (128x64 halves)
    #pragma unroll
    for (int it = 0; it < 4; it++) {
        int idx = tid + it*256;
        int r = idx >> 3, ch = idx & 7;
        uint4 v = *(const uint4*)(qkv + (tok0 + q0 + r)*(size_t)(3*DD) + h*HD + ch*8);
        *(uint4*)(Qs + r*QSTR + ch*8) = v;
    }
    __syncthreads();
    int qrow = q0 + wid*16;
    uint32_t qf[4][4];
    #pragma unroll
    for (int kg = 0; kg < 4; kg++)
        ldsm4(qf[kg], qs_u32 + ((wid*16 + ar)*QSTR + kg*16 + ac)*2);

    float oacc[8][4];
    #pragma unroll
    for (int nf = 0; nf < 8; nf++)
        #pragma unroll
        for (int i = 0; i < 4; i++) oacc[nf][i] = 0.f;
    float m0r = -1e30f, m1r = -1e30f, l0r = 0.f, l1r = 0.f;

    for (int jt = 0; jt <= jmax; jt++) {
        int j0 = jt * 64;
        int buf = jt & 1;
        CP_WAIT0();                 // tile jt landed (this thread)
        __syncthreads();            // tile jt visible to all; other buf free (jt-1 consumed)
        if (jt < jmax) {            // prefetch tile jt+1 into other buf
            int nb = (jt + 1) & 1;
            int nj0 = (jt + 1) * 64;
            #pragma unroll
            for (int it = 0; it < 2; it++) {
                int idx = tid + it*256;
                int r = idx >> 3, ch = idx & 7;
                const __half* gk = qkv + (tok0 + nj0 + r)*(size_t)(3*DD) + DD + h*HD + ch*8;
                cp16(ks_u32 + ((nb*64 + r)*QSTR + ch*8)*2, gk);
                cp16(vs_u32 + ((nb*64 + r)*QSTR + ch*8)*2, gk + DD);
            }
        }
        CP_COMMIT();
        uint32_t kb = ks_u32 + buf*64*QSTR*2;
        uint32_t vb = vs_u32 + buf*64*QSTR*2;
        if (j0 <= qrow + 15) {
            // S = Q K^T (16x64 per warp)
            float sacc[8][4];
            #pragma unroll
            for (int nf = 0; nf < 8; nf++)
                #pragma unroll
                for (int i = 0; i < 4; i++) sacc[nf][i] = 0.f;
            #pragma unroll
            for (int p = 0; p < 2; p++) {
                #pragma unroll
                for (int nf = 0; nf < 8; nf++) {
                    uint32_t kf[4];
                    ldsm4(kf, kb + ((nf*8 + br)*QSTR + p*32 + bc)*2);
                    mma_f16(sacc[nf], qf[2*p][0], qf[2*p][1], qf[2*p][2], qf[2*p][3], kf[0], kf[1]);
                    mma_f16(sacc[nf], qf[2*p+1][0], qf[2*p+1][1], qf[2*p+1][2], qf[2*p+1][3], kf[2], kf[3]);
                }
            }
            // causal mask near the diagonal
            if (j0 + 63 > qrow) {
                #pragma unroll
                for (int nf = 0; nf < 8; nf++) {
                    int col = j0 + nf*8 + 2*c;
                    if (col     > qrow + g)     sacc[nf][0] = -1e30f;
                    if (col + 1 > qrow + g)     sacc[nf][1] = -1e30f;
                    if (col     > qrow + 8 + g) sacc[nf][2] = -1e30f;
                    if (col + 1 > qrow + 8 + g) sacc[nf][3] = -1e30f;
                }
            }
            // online softmax (rows live in 4 lanes sharing g)
            float mx0 = -1e30f, mx1 = -1e30f;
            #pragma unroll
            for (int nf = 0; nf < 8; nf++) {
                mx0 = fmaxf(mx0, fmaxf(sacc[nf][0], sacc[nf][1]));
                mx1 = fmaxf(mx1, fmaxf(sacc[nf][2], sacc[nf][3]));
            }
            mx0 = fmaxf(mx0, __shfl_xor_sync(0xffffffffu, mx0, 1));
            mx0 = fmaxf(mx0, __shfl_xor_sync(0xffffffffu, mx0, 2));
            mx1 = fmaxf(mx1, __shfl_xor_sync(0xffffffffu, mx1, 1));
            mx1 = fmaxf(mx1, __shfl_xor_sync(0xffffffffu, mx1, 2));
            float nm0 = fmaxf(m0r, mx0), nm1 = fmaxf(m1r, mx1);
            float al0 = __expf(m0r - nm0), al1 = __expf(m1r - nm1);
            float sum0 = 0.f, sum1 = 0.f;
            #pragma unroll
            for (int nf = 0; nf < 8; nf++) {
                float p0 = __expf(sacc[nf][0] - nm0);
                float p1 = __expf(sacc[nf][1] - nm0);
                float p2 = __expf(sacc[nf][2] - nm1);
                float p3 = __expf(sacc[nf][3] - nm1);
                sacc[nf][0] = p0; sacc[nf][1] = p1; sacc[nf][2] = p2; sacc[nf][3] = p3;
                sum0 += p0 + p1; sum1 += p2 + p3;
            }
            sum0 += __shfl_xor_sync(0xffffffffu, sum0, 1);
            sum0 += __shfl_xor_sync(0xffffffffu, sum0, 2);
            sum1 += __shfl_xor_sync(0xffffffffu, sum1, 1);
            sum1 += __shfl_xor_sync(0xffffffffu, sum1, 2);
            l0r = l0r*al0 + sum0; l1r = l1r*al1 + sum1;
            m0r = nm0; m1r = nm1;
            // P fragments stay in registers (C layout == A layout)
            uint32_t pa[4][4];
            #pragma unroll
            for (int ks = 0; ks < 4; ks++) {
                pa[ks][0] = packh2(sacc[2*ks][0],   sacc[2*ks][1]);
                pa[ks][1] = packh2(sacc[2*ks][2],   sacc[2*ks][3]);
                pa[ks][2] = packh2(sacc[2*ks+1][0], sacc[2*ks+1][1]);
                pa[ks][3] = packh2(sacc[2*ks+1][2], sacc[2*ks+1][3]);
            }
            // rescale O
            #pragma unroll
            for (int nf = 0; nf < 8; nf++) {
                oacc[nf][0] *= al0; oacc[nf][1] *= al0;
                oacc[nf][2] *= al1; oacc[nf][3] *= al1;
            }
            // O += P @ V  (V via trans-ldmatrix)
            #pragma unroll
            for (int p = 0; p < 2; p++) {
                #pragma unroll
                for (int nf = 0; nf < 8; nf++) {
                    uint32_t vf[4];
                    ldsm4t(vf, vb + ((p*32 + lane)*QSTR + nf*8)*2);
                    mma_f16(oacc[nf], pa[2*p][0], pa[2*p][1], pa[2*p][2], pa[2*p][3], vf[0], vf[1]);
                    mma_f16(oacc[nf], pa[2*p+1][0], pa[2*p+1][1], pa[2*p+1][2], pa[2*p+1][3], vf[2], vf[3]);
                }
            }
        }
    }
    // epilogue -> half
    float inv0 = 1.f / l0r, inv1 = 1.f / l1r;
    #pragma unroll
    for (int nf = 0; nf < 8; nf++) {
        int col = h*HD + nf*8 + 2*c;
        size_t r0 = (tok0 + qrow + g    )*(size_t)DD + col;
        size_t r1 = (tok0 + qrow + 8 + g)*(size_t)DD + col;
        *(uint32_t*)(o + r0) = packh2(oacc[nf][0]*inv0, oacc[nf][1]*inv0);
        *(uint32_t*)(o + r1) = packh2(oacc[nf][2]*inv1, oacc[nf][3]*inv1);
    }
}

// ---------------- launch ----------------
extern "C" void kernel_launch(void* const* d_in, const int* in_sizes, int n_in,
                              void* d_out, int out_size) {
    const float* x        = (const float*)d_in[0];
    const float* qkv_w    = (const float*)d_in[2];
    const float* out_w    = (const float*)d_in[3];
    const float* gate_w   = (const float*)d_in[4];
    const float* gate_b   = (const float*)d_in[5];
    const float* w12      = (const float*)d_in[6];
    const float* w3       = (const float*)d_in[7];
    const float* hh_vs    = (const float*)d_in[8];
    const float* inv_freq = (const float*)d_in[9];
    const float* rope_pos = (const float*)d_in[10];
    float* out = (float*)d_out;

    __half *xn, *qkv, *o_, *oproj, *ffnin, *wf, *wo, *wg, *w12r, *w3r;
    float *x_, *Qm;
    cudaGetSymbolAddress((void**)&xn,    g_xn);
    cudaGetSymbolAddress((void**)&qkv,   g_qkv);
    cudaGetSymbolAddress((void**)&o_,    g_o);
    cudaGetSymbolAddress((void**)&oproj, g_oproj);
    cudaGetSymbolAddress((void**)&x_,    g_x);
    cudaGetSymbolAddress((void**)&ffnin, g_ffnin);
    cudaGetSymbolAddress((void**)&Qm,    g_Q);
    cudaGetSymbolAddress((void**)&wf,    g_w);
    cudaGetSymbolAddress((void**)&wo,    g_wo);
    cudaGetSymbolAddress((void**)&wg,    g_wg);
    cudaGetSymbolAddress((void**)&w12r,  g_w12r);
    cudaGetSymbolAddress((void**)&w3r,   g_w3r);

    static bool attr_set = false;
    static cudaStream_t s_side = nullptr;
    static cudaEvent_t ev_fork = nullptr, ev_join = nullptr;
    if (!attr_set) {
        cudaFuncSetAttribute(flashm_k, cudaFuncAttributeMaxDynamicSharedMemorySize, SMEM_FLASH);
        cudaFuncSetAttribute(tgemm_k, cudaFuncAttributeMaxDynamicSharedMemorySize, TG_SMEM);
        cudaFuncSetAttribute(gemm12_k, cudaFuncAttributeMaxDynamicSharedMemorySize, TG_SMEM);
        cudaStreamCreateWithFlags(&s_side, cudaStreamNonBlocking);
        cudaEventCreateWithFlags(&ev_fork, cudaEventDisableTiming);
        cudaEventCreateWithFlags(&ev_join, cudaEventDisableTiming);
        attr_set = true;
    }

    // fork: weight conversions on side stream (independent of activations)
    cudaEventRecord(ev_fork, 0);
    cudaStreamWaitEvent(s_side, ev_fork, 0);
    cvth_k<<<(DD*DD/4 + 255)/256, 256, 0, s_side>>>(out_w, wo, DD*DD/4);
    cvth_k<<<(DD*DD/4 + 255)/256, 256, 0, s_side>>>(gate_w, wg, DD*DD/4);
    cvth_k<<<(2*FFN*DD/4 + 255)/256, 256, 0, s_side>>>(w12, w12r, 2*FFN*DD/4);
    cvth_k<<<(DD*FFN/4 + 255)/256, 256, 0, s_side>>>(w3, w3r, DD*FFN/4);
    cudaEventRecord(ev_join, s_side);

    // main stream
    rmsnorm_k<<<MM, 256>>>(x, xn);
    hh_k<<<1, 256>>>(hh_vs, Qm);
    foldw2_k<<<dim3(8, 32), 256>>>(qkv_w, Qm, wf);
    cvth_k<<<(DD*DD/4 + 255)/256, 256>>>(qkv_w + 2*DD*DD, wf + 2*DD*DD, DD*DD/4);
    tgemm_k<<<dim3((3*DD)/128, MM/128), 256, TG_SMEM>>>(xn, wf, qkv, MM, 3*DD, DD,
                                                        nullptr, nullptr, nullptr, 1);
    rope_k<<<(MM*512)/256, 256>>>(qkv, inv_freq, rope_pos);
    flashm_k<<<dim3(SS/128, BB*HH), 256, SMEM_FLASH>>>(qkv, o_);
    // join: converted weights needed from here on
    cudaStreamWaitEvent(0, ev_join, 0);
    tgemm_k<<<dim3(DD/128, MM/128), 256, TG_SMEM>>>(o_, wo, oproj, MM, DD, DD,
                                                    nullptr, nullptr, nullptr, 1);
    // gate GEMM fused: x_ = x + oproj * sigmoid(oproj@gate_w^T + b)   (fp32 out)
    tgemm_k<<<dim3(DD/128, MM/128), 256, TG_SMEM>>>(oproj, wg, x_, MM, DD, DD,
                                                    gate_b, x, oproj, 0);
    rmsnorm_k<<<MM, 256>>>(x_, xn);
    gemm12_k<<<dim3(FFN/64, MM/128), 256, TG_SMEM>>>(xn, w12r, ffnin);
    tgemm_k<<<dim3(DD/128, MM/128), 256, TG_SMEM>>>(ffnin, w3r, out, MM, DD, FFN,
                                                    nullptr, x_, nullptr, 0);
}